// round 2
// baseline (speedup 1.0000x reference)
#include <cuda_runtime.h>
#include <cuda_bf16.h>
#include <cstddef>

#define NNODES 100000
#define NEDGES 500000
#define FEAT   128

// ---------------- scratch (device globals; no allocations allowed) ----------
__device__ int   g_cnt[NNODES];
__device__ int   g_rowoff[NNODES + 1];
__device__ int   g_cursor[NNODES];
__device__ float g_dinv[NNODES];
__device__ int   g_esrc[NEDGES];
__device__ float g_bufA[(size_t)NNODES * FEAT];
__device__ float g_bufB[(size_t)NNODES * FEAT];
__device__ float g_bufY[(size_t)NNODES * FEAT];
__device__ int   g_bsum[128];
__device__ int   g_boff[128];

// ---------------- CSR build --------------------------------------------------
__global__ void k_init_cnt() {
    int i = blockIdx.x * blockDim.x + threadIdx.x;
    if (i < NNODES) g_cnt[i] = 0;
}

__global__ void k_count(const int* __restrict__ dst) {
    int e = blockIdx.x * blockDim.x + threadIdx.x;
    if (e < NEDGES) atomicAdd(&g_cnt[dst[e]], 1);
}

// block scans 1024 counts (256 thr x 4), writes exclusive partials + block sum
__global__ void k_scan1() {
    __shared__ int sh[256];
    int t = threadIdx.x;
    int base = blockIdx.x * 1024;
    int v[4];
    int s = 0;
#pragma unroll
    for (int j = 0; j < 4; j++) {
        int idx = base + t * 4 + j;
        v[j] = (idx < NNODES) ? g_cnt[idx] : 0;
        s += v[j];
    }
    sh[t] = s;
    __syncthreads();
    for (int off = 1; off < 256; off <<= 1) {
        int x = (t >= off) ? sh[t - off] : 0;
        __syncthreads();
        sh[t] += x;
        __syncthreads();
    }
    int excl = sh[t] - s;
    if (t == 255) g_bsum[blockIdx.x] = sh[255];
    int run = excl;
#pragma unroll
    for (int j = 0; j < 4; j++) {
        int idx = base + t * 4 + j;
        if (idx < NNODES) g_rowoff[idx] = run;
        run += v[j];
    }
}

__global__ void k_scan2(int nb) {
    __shared__ int sh[128];
    int t = threadIdx.x;
    int v = (t < nb) ? g_bsum[t] : 0;
    sh[t] = v;
    __syncthreads();
    for (int off = 1; off < 128; off <<= 1) {
        int x = (t >= off) ? sh[t - off] : 0;
        __syncthreads();
        sh[t] += x;
        __syncthreads();
    }
    g_boff[t] = sh[t] - v;
}

__global__ void k_finalize() {
    int i = blockIdx.x * blockDim.x + threadIdx.x;
    if (i < NNODES) {
        int r = g_rowoff[i] + g_boff[i >> 10];
        g_rowoff[i] = r;
        g_cursor[i] = r;
        g_dinv[i] = rsqrtf((float)(g_cnt[i] + 1));
    }
    if (i == 0) g_rowoff[NNODES] = NEDGES;
}

__global__ void k_fill(const int* __restrict__ src, const int* __restrict__ dst) {
    int e = blockIdx.x * blockDim.x + threadIdx.x;
    if (e < NEDGES) {
        int p = atomicAdd(&g_cursor[dst[e]], 1);
        g_esrc[p] = src[e];
    }
}

// ---------------- GEMM:  Y[i][c] = dinv[i] * sum_k X[i][k] * W[k][c] --------
// X: [N,128], W: [128,Mout], Y: [N,Mout].  128x128 tile, 256 thr, 8x8 blocking.
__global__ __launch_bounds__(256) void k_gemm(const float* __restrict__ X,
                                              const float* __restrict__ W,
                                              float* __restrict__ Y, int Mout) {
    extern __shared__ float smem[];
    float* Xs = smem;               // 128 x 129
    float* Ws = smem + 128 * 129;   // 128 x 128

    int t = threadIdx.x;
    int row0 = blockIdx.x * 128;

    // load W (zero-padded to 128 cols)
    for (int idx = t; idx < 128 * 128; idx += 256) {
        int k = idx >> 7, c = idx & 127;
        Ws[idx] = (c < Mout) ? W[k * Mout + c] : 0.f;
    }
    // load X tile (float4), zero-fill OOB rows
    for (int idx = t; idx < 128 * 32; idx += 256) {
        int r = idx >> 5, kc = (idx & 31) * 4;
        int grow = row0 + r;
        float4 v = (grow < NNODES)
                       ? *(const float4*)(X + (size_t)grow * 128 + kc)
                       : make_float4(0.f, 0.f, 0.f, 0.f);
        float* p = &Xs[r * 129 + kc];
        p[0] = v.x; p[1] = v.y; p[2] = v.z; p[3] = v.w;
    }
    __syncthreads();

    int tx = t & 15, ty = t >> 4;
    int r0 = ty * 8, c0 = tx * 8;
    float acc[8][8];
#pragma unroll
    for (int i = 0; i < 8; i++)
#pragma unroll
        for (int j = 0; j < 8; j++) acc[i][j] = 0.f;

#pragma unroll 8
    for (int k = 0; k < 128; k++) {
        float a[8];
#pragma unroll
        for (int i = 0; i < 8; i++) a[i] = Xs[(r0 + i) * 129 + k];
        float4 b0 = *(const float4*)&Ws[k * 128 + c0];
        float4 b1 = *(const float4*)&Ws[k * 128 + c0 + 4];
        float b[8] = {b0.x, b0.y, b0.z, b0.w, b1.x, b1.y, b1.z, b1.w};
#pragma unroll
        for (int i = 0; i < 8; i++)
#pragma unroll
            for (int j = 0; j < 8; j++) acc[i][j] = fmaf(a[i], b[j], acc[i][j]);
    }

#pragma unroll
    for (int i = 0; i < 8; i++) {
        int gr = row0 + r0 + i;
        if (gr >= NNODES) continue;
        float dv = g_dinv[gr];
        if (Mout == 128) {
            float4 o0 = make_float4(dv * acc[i][0], dv * acc[i][1],
                                    dv * acc[i][2], dv * acc[i][3]);
            float4 o1 = make_float4(dv * acc[i][4], dv * acc[i][5],
                                    dv * acc[i][6], dv * acc[i][7]);
            *(float4*)(Y + (size_t)gr * 128 + c0) = o0;
            *(float4*)(Y + (size_t)gr * 128 + c0 + 4) = o1;
        } else {
#pragma unroll
            for (int j = 0; j < 8; j++) {
                int c = c0 + j;
                if (c < Mout) Y[(size_t)gr * Mout + c] = dv * acc[i][j];
            }
        }
    }
}

// ---------------- aggregation: warp per node ---------------------------------
// out[i] = relu?( dinv[i] * (Ys[i] + sum_{j in-edges} Ys[esrc[j]]) + bias )
__global__ void k_agg(const float* __restrict__ Y, const float* __restrict__ bias,
                      float* __restrict__ Hout, int Mout, int dorelu) {
    int warp = (blockIdx.x * blockDim.x + threadIdx.x) >> 5;
    int lane = threadIdx.x & 31;
    if (warp >= NNODES) return;
    int f = lane * 4;
    if (f >= Mout) return;

    int beg = g_rowoff[warp];
    int end = g_rowoff[warp + 1];

    float4 s = *(const float4*)(Y + (size_t)warp * Mout + f);  // self loop
    for (int j = beg; j < end; j++) {
        int sidx = __ldg(&g_esrc[j]);
        float4 v = __ldg((const float4*)(Y + (size_t)sidx * Mout + f));
        s.x += v.x; s.y += v.y; s.z += v.z; s.w += v.w;
    }
    float dv = g_dinv[warp];
    float4 bb = *(const float4*)(bias + f);
    float4 o = make_float4(fmaf(dv, s.x, bb.x), fmaf(dv, s.y, bb.y),
                           fmaf(dv, s.z, bb.z), fmaf(dv, s.w, bb.w));
    if (dorelu) {
        o.x = fmaxf(o.x, 0.f); o.y = fmaxf(o.y, 0.f);
        o.z = fmaxf(o.z, 0.f); o.w = fmaxf(o.w, 0.f);
    }
    *(float4*)(Hout + (size_t)warp * Mout + f) = o;
}

// ---------------- launch -----------------------------------------------------
extern "C" void kernel_launch(void* const* d_in, const int* in_sizes, int n_in,
                              void* d_out, int out_size) {
    const float* x = (const float*)d_in[0];
    const int* ei = (const int*)d_in[1];
    const int* src = ei;
    const int* dst = ei + NEDGES;
    const float* W0 = (const float*)d_in[2];
    const float* b0 = (const float*)d_in[3];
    const float* W1 = (const float*)d_in[4];
    const float* b1 = (const float*)d_in[5];
    const float* W2 = (const float*)d_in[6];
    const float* b2 = (const float*)d_in[7];
    const float* W3 = (const float*)d_in[8];
    const float* b3 = (const float*)d_in[9];
    float* out = (float*)d_out;

    float *bufA, *bufB, *bufY;
    cudaGetSymbolAddress((void**)&bufA, g_bufA);
    cudaGetSymbolAddress((void**)&bufB, g_bufB);
    cudaGetSymbolAddress((void**)&bufY, g_bufY);

    const int NT = 256;
    int gN = (NNODES + NT - 1) / NT;   // 391
    int gE = (NEDGES + NT - 1) / NT;   // 1954
    int gScan = (NNODES + 1023) / 1024; // 98

    // CSR + norm build
    k_init_cnt<<<gN, NT>>>();
    k_count<<<gE, NT>>>(dst);
    k_scan1<<<gScan, NT>>>();
    k_scan2<<<1, 128>>>(gScan);
    k_finalize<<<gN, NT>>>();
    k_fill<<<gE, NT>>>(src, dst);

    size_t shmem = (128 * 129 + 128 * 128) * sizeof(float);  // 131584
    static int smem_set = 0;
    if (!smem_set) {
        cudaFuncSetAttribute(k_gemm, cudaFuncAttributeMaxDynamicSharedMemorySize,
                             (int)shmem);
        smem_set = 1;
    }

    int gGemm = (NNODES + 127) / 128;          // 782
    int gAgg = (NNODES * 32 + NT - 1) / NT;    // 12500

    // layer 0: x -> bufA
    k_gemm<<<gGemm, NT, shmem>>>(x, W0, bufY, 128);
    k_agg<<<gAgg, NT>>>(bufY, b0, bufA, 128, 1);
    // layer 1: bufA -> bufB
    k_gemm<<<gGemm, NT, shmem>>>(bufA, W1, bufY, 128);
    k_agg<<<gAgg, NT>>>(bufY, b1, bufB, 128, 1);
    // layer 2: bufB -> bufA
    k_gemm<<<gGemm, NT, shmem>>>(bufB, W2, bufY, 128);
    k_agg<<<gAgg, NT>>>(bufY, b2, bufA, 128, 1);
    // layer 3: bufA -> out (C=40, no relu)
    k_gemm<<<gGemm, NT, shmem>>>(bufA, W3, bufY, 40);
    k_agg<<<gAgg, NT>>>(bufY, b3, out, 40, 0);
}